// round 8
// baseline (speedup 1.0000x reference)
#include <cuda_runtime.h>
#include <cuda_bf16.h>
#include <cstdint>

#define NV 1000000
#define KK 27
#define MT 128
#define NTILE 7813              // ceil(NV/128)
#define NTILP 7816              // 977*8
#define NSEGA (NTILP*KK)        // 211032
#define PB 977

// ---------------- scratch ----------------
__device__ uint4 g_xb[NV];           // x as bf16 [N,8]
__device__ uint4 g_t1b[NV * 4];      // [N,32] bf16
__device__ uint4 g_t5b[NV * 4];
__device__ uint4 g_sab[NV];          // [N,8] bf16
__device__ uint4 g_sbb[NV];
__device__ unsigned g_ent[NV * KK];  // src(20b) | dl(7b)<<20, CSR per (tile,k)
__device__ int   g_segcnt[NSEGA];
__device__ int   g_segoff[NSEGA + 1];
__device__ __nv_bfloat16 g_wimg[71680];  // pre-swizzled, zero-padded B images
// wimg offsets (bf16): c1 0, c2 14336, c3 21504, c4 25088, c5 28672, c6 43008

// ---------------- helpers ----------------
__device__ __forceinline__ uint32_t smem_u32(const void* p) {
    uint32_t a;
    asm("{ .reg .u64 t; cvta.to.shared.u64 t, %1; cvt.u32.u64 %0, t; }" : "=r"(a) : "l"(p));
    return a;
}
static __device__ __forceinline__ uint32_t pkbf(float lo, float hi) {
    uint32_t r; asm("cvt.rn.bf16x2.f32 %0, %1, %2;" : "=r"(r) : "f"(hi), "f"(lo)); return r;
}
__device__ __forceinline__ uint32_t sw128(uint32_t b) { return b ^ ((b >> 3) & 0x70); }

__device__ __forceinline__ void ldsm4(uint32_t* r, uint32_t addr) {
    asm volatile("ldmatrix.sync.aligned.m8n8.x4.shared.b16 {%0,%1,%2,%3}, [%4];"
                 : "=r"(r[0]), "=r"(r[1]), "=r"(r[2]), "=r"(r[3]) : "r"(addr));
}
__device__ __forceinline__ void ldsm2(uint32_t* r, uint32_t addr) {
    asm volatile("ldmatrix.sync.aligned.m8n8.x2.shared.b16 {%0,%1}, [%2];"
                 : "=r"(r[0]), "=r"(r[1]) : "r"(addr));
}
__device__ __forceinline__ void mma16816(float* c, const uint32_t* a, const uint32_t* b) {
    asm volatile("mma.sync.aligned.m16n8k16.row.col.f32.bf16.bf16.f32 "
                 "{%0,%1,%2,%3}, {%4,%5,%6,%7}, {%8,%9}, {%0,%1,%2,%3};"
                 : "+f"(c[0]), "+f"(c[1]), "+f"(c[2]), "+f"(c[3])
                 : "r"(a[0]), "r"(a[1]), "r"(a[2]), "r"(a[3]), "r"(b[0]), "r"(b[1]));
}

// ---------------- prep 1: mask probe + per-(tile,k) counts + x->bf16 ----------
__global__ __launch_bounds__(256) void prep_count(const unsigned char* __restrict__ m,
                                                  const float* __restrict__ x) {
    __shared__ int s_mode;
    const int tid = threadIdx.x;
    if (tid == 0) s_mode = 1;
    __syncthreads();
    { unsigned char b = m[4 * tid + 1] | m[4 * tid + 2] | m[4 * tid + 3]; if (b) s_mode = 0; }
    __syncthreads();
    const int mode = s_mode;
    const int n0 = blockIdx.x * 1024 + tid * 4;
    const bool inb = n0 < NV;
    const int w = tid >> 5;
    if (inb) {  // x -> bf16
        const float4* xp = (const float4*)(x + (size_t)n0 * 8);
#pragma unroll
        for (int v = 0; v < 4; v++) {
            float4 a = xp[2 * v], b = xp[2 * v + 1];
            g_xb[n0 + v] = make_uint4(pkbf(a.x, a.y), pkbf(a.z, a.w),
                                      pkbf(b.x, b.y), pkbf(b.z, b.w));
        }
    }
    for (int k = 0; k < KK; k++) {
        int c = 0;
        if (inb) {
            if (mode == 0) {
                uchar4 v = *(const uchar4*)(m + (size_t)k * NV + n0);
                c = (v.x != 0) + (v.y != 0) + (v.z != 0) + (v.w != 0);
            } else {
                int4 v = *(const int4*)((const int*)m + (size_t)k * NV + n0);
                c = (v.x != 0) + (v.y != 0) + (v.z != 0) + (v.w != 0);
            }
        }
#pragma unroll
        for (int o = 16; o; o >>= 1) c += __shfl_down_sync(0xffffffffu, c, o);
        if ((tid & 31) == 0) g_segcnt[(blockIdx.x * 8 + w) * KK + k] = c;
    }
}

// ---------------- prep 2: block0 = scan ; blocks 1..70 = weight images ----------
__global__ __launch_bounds__(1024) void scan_wimg(const float* __restrict__ Wd0,
        const float* __restrict__ Wd1, const float* __restrict__ Wd2,
        const float* __restrict__ Wu0, const float* __restrict__ Wu1,
        const float* __restrict__ Wu2) {
    const int t = threadIdx.x;
    if (blockIdx.x == 0) {
        __shared__ int s[1024];
        const int CH = (NSEGA + 1023) / 1024;   // 207
        const int base = t * CH, end = min(base + CH, NSEGA);
        int sum = 0;
        for (int i = base; i < end; i++) sum += g_segcnt[i];
        s[t] = sum;
        __syncthreads();
#pragma unroll
        for (int off = 1; off < 1024; off <<= 1) {
            int v = (t >= off) ? s[t - off] : 0;
            __syncthreads();
            s[t] += v;
            __syncthreads();
        }
        int run = s[t] - sum;
        for (int i = base; i < end; i++) { g_segoff[i] = run; run += g_segcnt[i]; }
        if (t == 1023) g_segoff[NSEGA] = s[1023];
        return;
    }
    int e = (blockIdx.x - 1) * 1024 + t;
    if (e >= 71680) return;
    int conv, off, N, TAPS, KPAD;
    if      (e < 14336) { conv = 0; off = 0;     N = 32; TAPS = 4; KPAD = 16; }
    else if (e < 21504) { conv = 1; off = 14336; N = 8;  TAPS = 2; KPAD = 32; }
    else if (e < 25088) { conv = 2; off = 21504; N = 8;  TAPS = 4; KPAD = 16; }
    else if (e < 28672) { conv = 3; off = 25088; N = 8;  TAPS = 4; KPAD = 16; }
    else if (e < 43008) { conv = 4; off = 28672; N = 32; TAPS = 4; KPAD = 16; }
    else                { conv = 5; off = 43008; N = 32; TAPS = 2; KPAD = 32; }
    int rem = e - off;
    int r = rem / (N * 64); rem -= r * N * 64;
    int n = rem >> 6;
    int j = rem & 63;
    int tp = j / KPAD, ci = j % KPAD;
    int k = r * TAPS + tp;
    float v = 0.f;
    if (k < KK) {
        if (conv == 0) { if (ci < 8) v = Wd0[k * 1024 + ci * 32 + n] + Wd0[k * 1024 + (8 + ci) * 32 + n]
                                       + Wd0[k * 1024 + (16 + ci) * 32 + n] + Wd0[k * 1024 + (24 + ci) * 32 + n]; }
        else if (conv == 1) { v = Wd1[k * 256 + ci * 8 + n]; }
        else if (conv == 2) { if (ci < 8) v = Wd2[k * 64 + ci * 8 + n]; }
        else if (conv == 3) { if (ci < 8) v = Wu0[k * 64 + ci * 8 + n]; }
        else if (conv == 4) { if (ci < 8) v = Wu1[k * 256 + ci * 32 + n]; }
        else                { v = Wu2[k * 1024 + ci * 32 + n]; }
    }
    uint32_t byte = (uint32_t)n * 128 + (uint32_t)j * 2;
    g_wimg[off + r * N * 64 + (sw128(byte) >> 1)] = __float2bfloat16(v);
}

// ---------------- prep 3: fill entries (per-warp smem cursors) ----------------
__global__ __launch_bounds__(256) void prep_fill(const unsigned char* __restrict__ m,
                                                 const int* __restrict__ idx) {
    __shared__ int cur[216];
    __shared__ int s_mode;
    const int tid = threadIdx.x;
    if (tid < 216) cur[tid] = g_segoff[blockIdx.x * 216 + tid];
    if (tid == 0) s_mode = 1;
    __syncthreads();
    { unsigned char b = m[4 * tid + 1] | m[4 * tid + 2] | m[4 * tid + 3]; if (b) s_mode = 0; }
    __syncthreads();
    const int mode = s_mode;
    const int n0 = blockIdx.x * 1024 + tid * 4;
    if (n0 >= NV) return;
    const int w = tid >> 5;
    const unsigned dl0 = (unsigned)(n0 & 127) << 20;
    for (int k = 0; k < KK; k++) {
        int t0, t1, t2, t3;
        if (mode == 0) {
            uchar4 v = *(const uchar4*)(m + (size_t)k * NV + n0);
            t0 = v.x; t1 = v.y; t2 = v.z; t3 = v.w;
        } else {
            int4 v = *(const int4*)((const int*)m + (size_t)k * NV + n0);
            t0 = v.x; t1 = v.y; t2 = v.z; t3 = v.w;
        }
        const int* ip = idx + (size_t)k * NV + n0;
        int* cc = &cur[w * KK + k];
        if (t0) { int p = atomicAdd(cc, 1); g_ent[p] = (unsigned)ip[0] | dl0; }
        if (t1) { int p = atomicAdd(cc, 1); g_ent[p] = (unsigned)ip[1] | (dl0 + (1u << 20)); }
        if (t2) { int p = atomicAdd(cc, 1); g_ent[p] = (unsigned)ip[2] | (dl0 + (2u << 20)); }
        if (t3) { int p = atomicAdd(cc, 1); g_ent[p] = (unsigned)ip[3] | (dl0 + (3u << 20)); }
    }
}

// ---------------- gather / zero pass over compact entries ----------------
template <int CIN>
__device__ __forceinline__ void gpass(char* A, int segb, int r,
                                      int wid, int lane, bool zero,
                                      const uint4* __restrict__ in) {
    constexpr int TAPS = (CIN == 8) ? 4 : 2;
    const int tp = (CIN == 8) ? wid : (wid & 1);
    const int k = r * TAPS + tp;
    if (k >= KK) return;
    const int lo = g_segoff[segb + k], hi = g_segoff[segb + k + 1];
    const uint4 z = make_uint4(0, 0, 0, 0);
    if (CIN == 8) {
        for (int i = lo + lane; i < hi; i += 32) {
            unsigned e = g_ent[i];
            uint4 v = zero ? z : __ldg(in + (e & 0xFFFFFu));
            *(uint4*)(A + sw128((e >> 20) * 128 + tp * 32)) = v;
        }
    } else {
        const int j = lane & 3;
        for (int i = lo + (wid >> 1) * 8 + (lane >> 2); i < hi; i += 16) {
            unsigned e = g_ent[i];
            uint4 v = zero ? z : __ldg(in + (size_t)(e & 0xFFFFFu) * 4 + j);
            *(uint4*)(A + sw128((e >> 20) * 128 + tp * 64 + j * 16)) = v;
        }
    }
}

// ---------------- mma.sync sparse conv, compact-entry gather ----------------
// MODE 0: bf16 out = d ; MODE 1: bf16 out = x - d (NOUT=8) ; MODE 2: fp32 out = d + tile(x)
template <int CIN, int NOUT, int MODE>
__global__ __launch_bounds__(128) void conv_mma(const uint4* __restrict__ in,
        const uint4* __restrict__ wimg, const float* __restrict__ xres,
        void* __restrict__ outp) {
    constexpr int TAPS = (CIN == 8) ? 4 : 2;
    constexpr int R = (KK + TAPS - 1) / TAPS;   // 7 or 14
    constexpr int NTL = NOUT / 8;
    __shared__ __align__(1024) __nv_bfloat16 sA[MT * 64];    // 16KB
    __shared__ __align__(1024) __nv_bfloat16 sB[NOUT * 64];
    const int tile = blockIdx.x, tid = threadIdx.x, lane = tid & 31, wid = tid >> 5;
    const uint32_t abase = smem_u32(sA), bbase = smem_u32(sB);
    const int segb = tile * KK;

    {   // zero A once; thereafter only active slots are ever nonzero
        uint4 zz = make_uint4(0, 0, 0, 0);
        uint4* a4 = (uint4*)sA;
        for (int i = tid; i < MT * 8; i += 128) a4[i] = zz;
    }
    float acc[2][NTL][4];
#pragma unroll
    for (int mt = 0; mt < 2; mt++)
#pragma unroll
        for (int nt = 0; nt < NTL; nt++)
#pragma unroll
            for (int q = 0; q < 4; q++) acc[mt][nt][q] = 0.f;
    __syncthreads();

    for (int r = 0; r < R; r++) {
        if (r > 0) gpass<CIN>((char*)sA, segb, r - 1, wid, lane, true, in);
        __syncthreads();                       // zeros visible before new writes
        gpass<CIN>((char*)sA, segb, r, wid, lane, false, in);
        for (int i = tid; i < NOUT * 8; i += 128)
            ((uint4*)sB)[i] = __ldg(wimg + r * NOUT * 8 + i);
        __syncthreads();                       // A/B ready
        const int m0 = wid * 32;
#pragma unroll
        for (int ks = 0; ks < 4; ks++) {
            uint32_t a[2][4];
#pragma unroll
            for (int mt = 0; mt < 2; mt++) {
                uint32_t addr = abase + sw128((uint32_t)(m0 + mt * 16 + (lane & 15)) * 128
                                              + ks * 32 + ((lane >> 4) * 16));
                ldsm4(a[mt], addr);
            }
#pragma unroll
            for (int nt = 0; nt < NTL; nt++) {
                uint32_t b[2];
                uint32_t baddr = bbase + sw128((uint32_t)(nt * 8 + (lane & 7)) * 128
                                               + ks * 32 + (((lane >> 3) & 1) * 16));
                ldsm2(b, baddr);
                mma16816(acc[0][nt], a[0], b);
                mma16816(acc[1][nt], a[1], b);
            }
        }
        __syncthreads();                       // MMA reads done before next zeroing
    }

    // epilogue from register fragments
    const int rbase = tile * 128 + wid * 32;
#pragma unroll
    for (int mt = 0; mt < 2; mt++) {
#pragma unroll
        for (int h = 0; h < 2; h++) {
            const int n = rbase + mt * 16 + (lane >> 2) + h * 8;
            if (n >= NV) continue;
            if (NOUT == 32) {
                if (MODE == 2) {
                    const float2 xr = *(const float2*)(xres + (size_t)n * 8 + (lane & 3) * 2);
                    float* o = (float*)outp + (size_t)n * 32 + (lane & 3) * 2;
#pragma unroll
                    for (int nt = 0; nt < NTL; nt++) {
                        float c0 = acc[mt][nt][h * 2], c1 = acc[mt][nt][h * 2 + 1];
                        *(float2*)(o + nt * 8) = make_float2(c0 + xr.x, c1 + xr.y);
                    }
                } else {
                    uint32_t* o = (uint32_t*)outp + (size_t)n * 16 + (lane & 3);
#pragma unroll
                    for (int nt = 0; nt < NTL; nt++)
                        o[nt * 4] = pkbf(acc[mt][nt][h * 2], acc[mt][nt][h * 2 + 1]);
                }
            } else {
                float c0 = acc[mt][0][h * 2], c1 = acc[mt][0][h * 2 + 1];
                if (MODE == 1) {
                    const float2 xr = *(const float2*)(xres + (size_t)n * 8 + (lane & 3) * 2);
                    c0 = xr.x - c0; c1 = xr.y - c1;
                }
                ((uint32_t*)outp)[(size_t)n * 4 + (lane & 3)] = pkbf(c0, c1);
            }
        }
    }
}

// ---------------- launcher ----------------
extern "C" void kernel_launch(void* const* d_in, const int* in_sizes, int n_in,
                              void* d_out, int out_size) {
    const float*         x    = (const float*)d_in[0];
    const int*           nidx = (const int*)d_in[1];
    const unsigned char* nmsk = (const unsigned char*)d_in[2];
    const float* Wd0 = (const float*)d_in[3];
    const float* Wd1 = (const float*)d_in[4];
    const float* Wd2 = (const float*)d_in[5];
    const float* Wu0 = (const float*)d_in[6];
    const float* Wu1 = (const float*)d_in[7];
    const float* Wu2 = (const float*)d_in[8];
    float* outp = (float*)d_out;

    void *p_xb, *p_t1, *p_t5, *p_sa, *p_sb, *p_w;
    cudaGetSymbolAddress(&p_xb, g_xb);
    cudaGetSymbolAddress(&p_t1, g_t1b);
    cudaGetSymbolAddress(&p_t5, g_t5b);
    cudaGetSymbolAddress(&p_sa, g_sab);
    cudaGetSymbolAddress(&p_sb, g_sbb);
    cudaGetSymbolAddress(&p_w,  g_wimg);
    const uint4* xb = (const uint4*)p_xb;
    uint4* t1b = (uint4*)p_t1;
    uint4* t5b = (uint4*)p_t5;
    uint4* sab = (uint4*)p_sa;
    uint4* sbb = (uint4*)p_sb;
    const uint4* wi = (const uint4*)p_w;   // bf16elems/8

    // prep: 3 launches -> conv1 is launch #4 (ncu target)
    prep_count<<<PB, 256>>>(nmsk, x);
    scan_wimg<<<71, 1024>>>(Wd0, Wd1, Wd2, Wu0, Wu1, Wu2);
    prep_fill<<<PB, 256>>>(nmsk, nidx);

    // conv chain
    conv_mma<8, 32, 0><<<NTILE, 128>>>(xb, wi + 0, nullptr, t1b);                   // conv1
    conv_mma<32, 8, 0><<<NTILE, 128>>>((const uint4*)t1b, wi + 1792, nullptr, sab); // conv2
    conv_mma<8,  8, 1><<<NTILE, 128>>>((const uint4*)sab, wi + 2688, x, sbb);       // conv3
    conv_mma<8,  8, 0><<<NTILE, 128>>>((const uint4*)sbb, wi + 3136, nullptr, sab); // conv4
    conv_mma<8, 32, 0><<<NTILE, 128>>>((const uint4*)sab, wi + 3584, nullptr, t5b); // conv5
    conv_mma<32, 32, 2><<<NTILE, 128>>>((const uint4*)t5b, wi + 5376, x, outp);     // conv6
    (void)in_sizes; (void)n_in; (void)out_size;
}

// round 9
// speedup vs baseline: 1.1998x; 1.1998x over previous
#include <cuda_runtime.h>
#include <cuda_bf16.h>
#include <cstdint>

#define NV 1000000
#define KK 27
#define MT 128
#define NTILE 7813              // ceil(NV/128)
#define NTILP 7816              // 977*8
#define NSEGA (NTILP*KK)
#define PB 977

// ---------------- scratch ----------------
__device__ uint4 g_xb[NV];           // x as bf16 [N,8]
__device__ uint4 g_t1b[NV * 4];      // [N,32] bf16
__device__ uint4 g_t5b[NV * 4];
__device__ uint4 g_sab[NV];          // [N,8] bf16
__device__ uint4 g_sbb[NV];
__device__ unsigned g_ent[NV * KK];  // src(20b) | dl(7b)<<20 | k(5b)<<27
__device__ int   g_segcnt[NSEGA];
__device__ int   g_segoff[NSEGA + 1];
__device__ __nv_bfloat16 g_wimg[56320];  // pre-swizzled, zero-padded B images
// wimg bf16 offsets: c1 0, c2 8192, c3 15360, c4 17408, c5 19456, c6 27648

// ---------------- helpers ----------------
__device__ __forceinline__ uint32_t smem_u32(const void* p) {
    uint32_t a;
    asm("{ .reg .u64 t; cvta.to.shared.u64 t, %1; cvt.u32.u64 %0, t; }" : "=r"(a) : "l"(p));
    return a;
}
static __device__ __forceinline__ uint32_t pkbf(float lo, float hi) {
    uint32_t r; asm("cvt.rn.bf16x2.f32 %0, %1, %2;" : "=r"(r) : "f"(hi), "f"(lo)); return r;
}
__device__ __forceinline__ uint32_t sw128(uint32_t b) { return b ^ ((b >> 3) & 0x70); }

__device__ __forceinline__ void ldsm4(uint32_t* r, uint32_t addr) {
    asm volatile("ldmatrix.sync.aligned.m8n8.x4.shared.b16 {%0,%1,%2,%3}, [%4];"
                 : "=r"(r[0]), "=r"(r[1]), "=r"(r[2]), "=r"(r[3]) : "r"(addr));
}
__device__ __forceinline__ void ldsm2(uint32_t* r, uint32_t addr) {
    asm volatile("ldmatrix.sync.aligned.m8n8.x2.shared.b16 {%0,%1}, [%2];"
                 : "=r"(r[0]), "=r"(r[1]) : "r"(addr));
}
__device__ __forceinline__ void mma16816(float* c, const uint32_t* a, const uint32_t* b) {
    asm volatile("mma.sync.aligned.m16n8k16.row.col.f32.bf16.bf16.f32 "
                 "{%0,%1,%2,%3}, {%4,%5,%6,%7}, {%8,%9}, {%0,%1,%2,%3};"
                 : "+f"(c[0]), "+f"(c[1]), "+f"(c[2]), "+f"(c[3])
                 : "r"(a[0]), "r"(a[1]), "r"(a[2]), "r"(a[3]), "r"(b[0]), "r"(b[1]));
}

// ---------------- prep 1: mask probe + per-(tile,k) counts + x->bf16 ----------
__global__ __launch_bounds__(256) void prep_count(const unsigned char* __restrict__ m,
                                                  const float* __restrict__ x) {
    __shared__ int s_mode;
    const int tid = threadIdx.x;
    if (tid == 0) s_mode = 1;
    __syncthreads();
    { unsigned char b = m[4 * tid + 1] | m[4 * tid + 2] | m[4 * tid + 3]; if (b) s_mode = 0; }
    __syncthreads();
    const int mode = s_mode;
    const int n0 = blockIdx.x * 1024 + tid * 4;
    const bool inb = n0 < NV;
    const int w = tid >> 5;
    if (inb) {
        const float4* xp = (const float4*)(x + (size_t)n0 * 8);
#pragma unroll
        for (int v = 0; v < 4; v++) {
            float4 a = xp[2 * v], b = xp[2 * v + 1];
            g_xb[n0 + v] = make_uint4(pkbf(a.x, a.y), pkbf(a.z, a.w),
                                      pkbf(b.x, b.y), pkbf(b.z, b.w));
        }
    }
    for (int k = 0; k < KK; k++) {
        int c = 0;
        if (inb) {
            if (mode == 0) {
                uchar4 v = *(const uchar4*)(m + (size_t)k * NV + n0);
                c = (v.x != 0) + (v.y != 0) + (v.z != 0) + (v.w != 0);
            } else {
                int4 v = *(const int4*)((const int*)m + (size_t)k * NV + n0);
                c = (v.x != 0) + (v.y != 0) + (v.z != 0) + (v.w != 0);
            }
        }
#pragma unroll
        for (int o = 16; o; o >>= 1) c += __shfl_down_sync(0xffffffffu, c, o);
        if ((tid & 31) == 0) g_segcnt[(blockIdx.x * 8 + w) * KK + k] = c;
    }
}

// ---------------- prep 2: block0 = scan ; blocks 1..55 = weight images ----------
__global__ __launch_bounds__(1024) void scan_wimg(const float* __restrict__ Wd0,
        const float* __restrict__ Wd1, const float* __restrict__ Wd2,
        const float* __restrict__ Wu0, const float* __restrict__ Wu1,
        const float* __restrict__ Wu2) {
    const int t = threadIdx.x;
    if (blockIdx.x == 0) {
        __shared__ int s[1024];
        const int CH = (NSEGA + 1023) / 1024;
        const int base = t * CH, end = min(base + CH, NSEGA);
        int sum = 0;
        for (int i = base; i < end; i++) sum += g_segcnt[i];
        s[t] = sum;
        __syncthreads();
#pragma unroll
        for (int off = 1; off < 1024; off <<= 1) {
            int v = (t >= off) ? s[t - off] : 0;
            __syncthreads();
            s[t] += v;
            __syncthreads();
        }
        int run = s[t] - sum;
        for (int i = base; i < end; i++) { g_segoff[i] = run; run += g_segcnt[i]; }
        if (t == 1023) g_segoff[NSEGA] = s[1023];
        return;
    }
    int e = (blockIdx.x - 1) * 1024 + t;
    if (e >= 56320) return;
    int conv, off, N, TPR;
    if      (e < 8192)  { conv = 0; off = 0;     N = 32; TPR = 8; }
    else if (e < 15360) { conv = 1; off = 8192;  N = 8;  TPR = 2; }
    else if (e < 17408) { conv = 2; off = 15360; N = 8;  TPR = 8; }
    else if (e < 19456) { conv = 3; off = 17408; N = 8;  TPR = 8; }
    else if (e < 27648) { conv = 4; off = 19456; N = 32; TPR = 8; }
    else                { conv = 5; off = 27648; N = 32; TPR = 2; }
    int rem = e - off;
    int r = rem / (N * 64); rem -= r * N * 64;
    int n = rem >> 6;
    int j = rem & 63;
    const int KW = 64 / TPR;            // tap width: 8 or 32
    int tp = j / KW, ci = j % KW;
    int k = r * TPR + tp;
    float v = 0.f;
    if (k < KK) {
        if (conv == 0)      v = Wd0[k * 1024 + ci * 32 + n] + Wd0[k * 1024 + (8 + ci) * 32 + n]
                              + Wd0[k * 1024 + (16 + ci) * 32 + n] + Wd0[k * 1024 + (24 + ci) * 32 + n];
        else if (conv == 1) v = Wd1[k * 256 + ci * 8 + n];
        else if (conv == 2) v = Wd2[k * 64 + ci * 8 + n];
        else if (conv == 3) v = Wu0[k * 64 + ci * 8 + n];
        else if (conv == 4) v = Wu1[k * 256 + ci * 32 + n];
        else                v = Wu2[k * 1024 + ci * 32 + n];
    }
    uint32_t byte = (uint32_t)n * 128 + (uint32_t)j * 2;
    g_wimg[off + r * N * 64 + (sw128(byte) >> 1)] = __float2bfloat16(v);
}

// ---------------- prep 3: fill entries (warp-prefix cursors, no atomics) -------
__global__ __launch_bounds__(256) void prep_fill(const unsigned char* __restrict__ m,
                                                 const int* __restrict__ idx) {
    __shared__ int s_mode;
    const int tid = threadIdx.x, lane = tid & 31, w = tid >> 5;
    if (tid == 0) s_mode = 1;
    __syncthreads();
    { unsigned char b = m[4 * tid + 1] | m[4 * tid + 2] | m[4 * tid + 3]; if (b) s_mode = 0; }
    __syncthreads();
    const int mode = s_mode;
    const int n0 = blockIdx.x * 1024 + tid * 4;
    const bool inb = n0 < NV;                 // keep all lanes for warp prefix
    const unsigned dl0 = inb ? ((unsigned)(n0 & 127) << 20) : 0u;
    int wbase = g_segoff[(size_t)(blockIdx.x * 8 + w) * KK];
    for (int k = 0; k < KK; k++) {
        int t0 = 0, t1 = 0, t2 = 0, t3 = 0;
        int4 iv = make_int4(0, 0, 0, 0);
        if (inb) {
            if (mode == 0) {
                uchar4 v = *(const uchar4*)(m + (size_t)k * NV + n0);
                t0 = v.x != 0; t1 = v.y != 0; t2 = v.z != 0; t3 = v.w != 0;
            } else {
                int4 v = *(const int4*)((const int*)m + (size_t)k * NV + n0);
                t0 = v.x != 0; t1 = v.y != 0; t2 = v.z != 0; t3 = v.w != 0;
            }
            iv = *(const int4*)(idx + (size_t)k * NV + n0);
        }
        int cnt = t0 + t1 + t2 + t3;
        int pre = cnt;
#pragma unroll
        for (int o = 1; o < 32; o <<= 1) {
            int v = __shfl_up_sync(0xffffffffu, pre, o);
            if (lane >= o) pre += v;
        }
        const int tot = __shfl_sync(0xffffffffu, pre, 31);
        int p = wbase + pre - cnt;
        const unsigned kb = (unsigned)k << 27;
        if (t0) g_ent[p++] = (unsigned)iv.x | dl0 | kb;
        if (t1) g_ent[p++] = (unsigned)iv.y | (dl0 + (1u << 20)) | kb;
        if (t2) g_ent[p++] = (unsigned)iv.z | (dl0 + (2u << 20)) | kb;
        if (t3) g_ent[p]   = (unsigned)iv.w | (dl0 + (3u << 20)) | kb;
        wbase += tot;
    }
}

// ---------------- gather/zero over a round's contiguous entry range ----------
template <int CIN, bool ZERO>
__device__ __forceinline__ void gpass(char* A, int lo, int hi, int kr0, int tid,
                                      const uint4* __restrict__ in) {
    const uint4 z = make_uint4(0, 0, 0, 0);
    if (CIN == 8) {
        for (int i = lo + tid; i < hi; i += 128) {
            unsigned e = g_ent[i];
            int tp = (int)(e >> 27) - kr0;
            uint4 v = ZERO ? z : __ldg(in + (e & 0xFFFFFu));
            *(uint4*)(A + sw128(((e >> 20) & 127) * 128 + tp * 16)) = v;
        }
    } else {
        for (int s = lo * 4 + tid; s < hi * 4; s += 128) {
            const int i = s >> 2, j = s & 3;
            unsigned e = g_ent[i];
            int tp = (int)(e >> 27) - kr0;
            uint4 v = ZERO ? z : __ldg(in + (size_t)(e & 0xFFFFFu) * 4 + j);
            *(uint4*)(A + sw128(((e >> 20) & 127) * 128 + tp * 64 + j * 16)) = v;
        }
    }
}

// ---------------- mma.sync sparse conv ----------------
// MODE 0: bf16 out = d ; MODE 1: bf16 out = x - d (NOUT=8) ; MODE 2: fp32 out = d + tile(x)
template <int CIN, int NOUT, int MODE>
__global__ __launch_bounds__(128) void conv_mma(const uint4* __restrict__ in,
        const uint4* __restrict__ wimg, const float* __restrict__ xres,
        void* __restrict__ outp) {
    constexpr int TPR = (CIN == 8) ? 8 : 2;
    constexpr int R = (KK + TPR - 1) / TPR;     // 4 or 14
    constexpr int NTL = NOUT / 8;
    __shared__ __align__(1024) __nv_bfloat16 sA[MT * 64];
    __shared__ __align__(1024) __nv_bfloat16 sB[NOUT * 64];
    const int tile = blockIdx.x, tid = threadIdx.x, lane = tid & 31, wid = tid >> 5;
    const uint32_t abase = smem_u32(sA), bbase = smem_u32(sB);
    const int segb = tile * KK;

    {   // zero A once; afterwards only active slots are nonzero
        uint4 zz = make_uint4(0, 0, 0, 0);
        uint4* a4 = (uint4*)sA;
        for (int i = tid; i < MT * 8; i += 128) a4[i] = zz;
    }
    float acc[2][NTL][4];
#pragma unroll
    for (int mt = 0; mt < 2; mt++)
#pragma unroll
        for (int nt = 0; nt < NTL; nt++)
#pragma unroll
            for (int q = 0; q < 4; q++) acc[mt][nt][q] = 0.f;

    int plo = 0, phi = 0, pk0 = 0;
    for (int r = 0; r < R; r++) {
        const int kr0 = r * TPR;
        const int kend = (kr0 + TPR < KK) ? kr0 + TPR : KK;
        const int lo = g_segoff[segb + kr0], hi = g_segoff[segb + kend];
        if (r > 0) gpass<CIN, true>((char*)sA, plo, phi, pk0, tid, in);
        __syncthreads();                       // zeros (or initial clear) visible
        gpass<CIN, false>((char*)sA, lo, hi, kr0, tid, in);
        for (int i = tid; i < NOUT * 8; i += 128)
            ((uint4*)sB)[i] = __ldg(wimg + r * NOUT * 8 + i);
        __syncthreads();                       // A/B ready
        const int m0 = wid * 32;
#pragma unroll
        for (int ks = 0; ks < 4; ks++) {
            uint32_t a[2][4];
#pragma unroll
            for (int mt = 0; mt < 2; mt++) {
                uint32_t addr = abase + sw128((uint32_t)(m0 + mt * 16 + (lane & 15)) * 128
                                              + ks * 32 + ((lane >> 4) * 16));
                ldsm4(a[mt], addr);
            }
#pragma unroll
            for (int nt = 0; nt < NTL; nt++) {
                uint32_t b[2];
                uint32_t baddr = bbase + sw128((uint32_t)(nt * 8 + (lane & 7)) * 128
                                               + ks * 32 + (((lane >> 3) & 1) * 16));
                ldsm2(b, baddr);
                mma16816(acc[0][nt], a[0], b);
                mma16816(acc[1][nt], a[1], b);
            }
        }
        __syncthreads();                       // MMA reads done before next zeroing
        plo = lo; phi = hi; pk0 = kr0;
    }

    const int rbase = tile * 128 + wid * 32;
#pragma unroll
    for (int mt = 0; mt < 2; mt++) {
#pragma unroll
        for (int h = 0; h < 2; h++) {
            const int n = rbase + mt * 16 + (lane >> 2) + h * 8;
            if (n >= NV) continue;
            if (NOUT == 32) {
                if (MODE == 2) {
                    const float2 xr = *(const float2*)(xres + (size_t)n * 8 + (lane & 3) * 2);
                    float* o = (float*)outp + (size_t)n * 32 + (lane & 3) * 2;
#pragma unroll
                    for (int nt = 0; nt < NTL; nt++) {
                        float c0 = acc[mt][nt][h * 2], c1 = acc[mt][nt][h * 2 + 1];
                        *(float2*)(o + nt * 8) = make_float2(c0 + xr.x, c1 + xr.y);
                    }
                } else {
                    uint32_t* o = (uint32_t*)outp + (size_t)n * 16 + (lane & 3);
#pragma unroll
                    for (int nt = 0; nt < NTL; nt++)
                        o[nt * 4] = pkbf(acc[mt][nt][h * 2], acc[mt][nt][h * 2 + 1]);
                }
            } else {
                float c0 = acc[mt][0][h * 2], c1 = acc[mt][0][h * 2 + 1];
                if (MODE == 1) {
                    const float2 xr = *(const float2*)(xres + (size_t)n * 8 + (lane & 3) * 2);
                    c0 = xr.x - c0; c1 = xr.y - c1;
                }
                ((uint32_t*)outp)[(size_t)n * 4 + (lane & 3)] = pkbf(c0, c1);
            }
        }
    }
}

// ---------------- launcher ----------------
extern "C" void kernel_launch(void* const* d_in, const int* in_sizes, int n_in,
                              void* d_out, int out_size) {
    const float*         x    = (const float*)d_in[0];
    const int*           nidx = (const int*)d_in[1];
    const unsigned char* nmsk = (const unsigned char*)d_in[2];
    const float* Wd0 = (const float*)d_in[3];
    const float* Wd1 = (const float*)d_in[4];
    const float* Wd2 = (const float*)d_in[5];
    const float* Wu0 = (const float*)d_in[6];
    const float* Wu1 = (const float*)d_in[7];
    const float* Wu2 = (const float*)d_in[8];
    float* outp = (float*)d_out;

    void *p_xb, *p_t1, *p_t5, *p_sa, *p_sb, *p_w;
    cudaGetSymbolAddress(&p_xb, g_xb);
    cudaGetSymbolAddress(&p_t1, g_t1b);
    cudaGetSymbolAddress(&p_t5, g_t5b);
    cudaGetSymbolAddress(&p_sa, g_sab);
    cudaGetSymbolAddress(&p_sb, g_sbb);
    cudaGetSymbolAddress(&p_w,  g_wimg);
    const uint4* xb = (const uint4*)p_xb;
    uint4* t1b = (uint4*)p_t1;
    uint4* t5b = (uint4*)p_t5;
    uint4* sab = (uint4*)p_sa;
    uint4* sbb = (uint4*)p_sb;
    const uint4* wi = (const uint4*)p_w;   // bf16 offsets / 8

    // prep: 3 launches -> conv1 is launch #4 (ncu target)
    prep_count<<<PB, 256>>>(nmsk, x);
    scan_wimg<<<56, 1024>>>(Wd0, Wd1, Wd2, Wu0, Wu1, Wu2);
    prep_fill<<<PB, 256>>>(nmsk, nidx);

    // conv chain (wimg uint4 offsets: 0,1024,1920,2176,2432,3456)
    conv_mma<8, 32, 0><<<NTILE, 128>>>(xb, wi + 0, nullptr, t1b);                   // conv1
    conv_mma<32, 8, 0><<<NTILE, 128>>>((const uint4*)t1b, wi + 1024, nullptr, sab); // conv2
    conv_mma<8,  8, 1><<<NTILE, 128>>>((const uint4*)sab, wi + 1920, x, sbb);       // conv3
    conv_mma<8,  8, 0><<<NTILE, 128>>>((const uint4*)sbb, wi + 2176, nullptr, sab); // conv4
    conv_mma<8, 32, 0><<<NTILE, 128>>>((const uint4*)sab, wi + 2432, nullptr, t5b); // conv5
    conv_mma<32, 32, 2><<<NTILE, 128>>>((const uint4*)t5b, wi + 3456, x, outp);     // conv6
    (void)in_sizes; (void)n_in; (void)out_size;
}

// round 10
// speedup vs baseline: 1.4703x; 1.2254x over previous
#include <cuda_runtime.h>
#include <cuda_bf16.h>
#include <cstdint>

#define NV 1000000
#define KK 27
#define MT 128
#define NTILE 7813              // ceil(NV/128)
#define ENTCAP 3456             // 128*27 max entries per tile

// ---------------- scratch ----------------
__device__ uint4 g_xb[NV];             // x as bf16 [N,8]
__device__ uint4 g_t1b[NV * 4];        // [N,32] bf16
__device__ uint4 g_t5b[NV * 4];
__device__ uint4 g_sab[NV];            // [N,8] bf16
__device__ uint4 g_sbb[NV];
__device__ unsigned g_ent[NTILE * ENTCAP];  // src(20b) | dl(7b)<<20 | k(5b)<<27
__device__ int   g_hdr[NTILE * 28];         // per-tile k-offsets (cumulative)
__device__ int   g_mode;                    // 0 = 1-byte mask, 1 = 4-byte
__device__ __nv_bfloat16 g_wimg[56320];     // pre-swizzled, zero-padded B sub-images
// wimg bf16 offsets: c1 0, c2 8192, c3 15360, c4 17408, c5 19456, c6 27648

// ---------------- helpers ----------------
__device__ __forceinline__ uint32_t smem_u32(const void* p) {
    uint32_t a;
    asm("{ .reg .u64 t; cvta.to.shared.u64 t, %1; cvt.u32.u64 %0, t; }" : "=r"(a) : "l"(p));
    return a;
}
static __device__ __forceinline__ uint32_t pkbf(float lo, float hi) {
    uint32_t r; asm("cvt.rn.bf16x2.f32 %0, %1, %2;" : "=r"(r) : "f"(hi), "f"(lo)); return r;
}
__device__ __forceinline__ uint32_t sw128(uint32_t b) { return b ^ ((b >> 3) & 0x70); }

__device__ __forceinline__ void ldsm4(uint32_t* r, uint32_t addr) {
    asm volatile("ldmatrix.sync.aligned.m8n8.x4.shared.b16 {%0,%1,%2,%3}, [%4];"
                 : "=r"(r[0]), "=r"(r[1]), "=r"(r[2]), "=r"(r[3]) : "r"(addr));
}
__device__ __forceinline__ void ldsm2(uint32_t* r, uint32_t addr) {
    asm volatile("ldmatrix.sync.aligned.m8n8.x2.shared.b16 {%0,%1}, [%2];"
                 : "=r"(r[0]), "=r"(r[1]) : "r"(addr));
}
__device__ __forceinline__ void mma16816(float* c, const uint32_t* a, const uint32_t* b) {
    asm volatile("mma.sync.aligned.m16n8k16.row.col.f32.bf16.bf16.f32 "
                 "{%0,%1,%2,%3}, {%4,%5,%6,%7}, {%8,%9}, {%0,%1,%2,%3};"
                 : "+f"(c[0]), "+f"(c[1]), "+f"(c[2]), "+f"(c[3])
                 : "r"(a[0]), "r"(a[1]), "r"(a[2]), "r"(a[3]), "r"(b[0]), "r"(b[1]));
}

// ---------------- prep 1: weight images + mask-dtype probe ----------------
__global__ __launch_bounds__(1024) void prep_wimg(const float* __restrict__ Wd0,
        const float* __restrict__ Wd1, const float* __restrict__ Wd2,
        const float* __restrict__ Wu0, const float* __restrict__ Wu1,
        const float* __restrict__ Wu2, const unsigned char* __restrict__ m) {
    const int t = threadIdx.x;
    if (blockIdx.x == 55) {   // probe block
        __shared__ int s_any;
        if (t == 0) s_any = 0;
        __syncthreads();
        if (t < 256) {
            unsigned char b = m[4 * t + 1] | m[4 * t + 2] | m[4 * t + 3];
            if (b) atomicOr(&s_any, 1);
        }
        __syncthreads();
        if (t == 0) g_mode = s_any ? 0 : 1;
        return;
    }
    int e = blockIdx.x * 1024 + t;          // blocks 0..54 cover 56320 exactly
    int conv, off, N, TPR;
    if      (e < 8192)  { conv = 0; off = 0;     N = 32; TPR = 8; }
    else if (e < 15360) { conv = 1; off = 8192;  N = 8;  TPR = 2; }
    else if (e < 17408) { conv = 2; off = 15360; N = 8;  TPR = 8; }
    else if (e < 19456) { conv = 3; off = 17408; N = 8;  TPR = 8; }
    else if (e < 27648) { conv = 4; off = 19456; N = 32; TPR = 8; }
    else                { conv = 5; off = 27648; N = 32; TPR = 2; }
    int rem = e - off;
    int r = rem / (N * 64); rem -= r * N * 64;
    int n = rem >> 6;
    int j = rem & 63;
    const int KW = 64 / TPR;
    int tp = j / KW, ci = j % KW;
    int k = r * TPR + tp;
    float v = 0.f;
    if (k < KK) {
        if (conv == 0)      v = Wd0[k * 1024 + ci * 32 + n] + Wd0[k * 1024 + (8 + ci) * 32 + n]
                              + Wd0[k * 1024 + (16 + ci) * 32 + n] + Wd0[k * 1024 + (24 + ci) * 32 + n];
        else if (conv == 1) v = Wd1[k * 256 + ci * 8 + n];
        else if (conv == 2) v = Wd2[k * 64 + ci * 8 + n];
        else if (conv == 3) v = Wu0[k * 64 + ci * 8 + n];
        else if (conv == 4) v = Wu1[k * 256 + ci * 32 + n];
        else                v = Wu2[k * 1024 + ci * 32 + n];
    }
    uint32_t byte = (uint32_t)n * 128 + (uint32_t)j * 2;
    g_wimg[off + r * N * 64 + (sw128(byte) >> 1)] = __float2bfloat16(v);
}

// ---------------- prep 2: single-pass fill (header + entries + x->bf16) --------
__global__ __launch_bounds__(128) void prep_fill(const unsigned char* __restrict__ m,
        const int* __restrict__ idx, const float* __restrict__ x) {
    __shared__ int s_base;
    __shared__ int s_wcnt[4];
    const int tile = blockIdx.x, tid = threadIdx.x, lane = tid & 31, w = tid >> 5;
    const int n = tile * 128 + tid;
    const bool inb = n < NV;
    const int mode = g_mode;
    if (inb) {   // x -> bf16
        const float4* xp = (const float4*)(x + (size_t)n * 8);
        float4 a = xp[0], b = xp[1];
        g_xb[n] = make_uint4(pkbf(a.x, a.y), pkbf(a.z, a.w),
                             pkbf(b.x, b.y), pkbf(b.z, b.w));
    }
    if (tid == 0) s_base = 0;
    int* hdr = g_hdr + tile * 28;
    unsigned* ent = g_ent + (size_t)tile * ENTCAP;
    const unsigned dlb = (unsigned)tid << 20;
    __syncthreads();
    for (int k = 0; k < KK; k++) {
        bool pred = false; int iv = 0;
        if (inb) {
            pred = (mode == 0) ? (m[(size_t)k * NV + n] != 0)
                               : (((const unsigned*)m)[(size_t)k * NV + n] != 0u);
            iv = idx[(size_t)k * NV + n];
        }
        const unsigned bal = __ballot_sync(0xffffffffu, pred);
        if (lane == 0) s_wcnt[w] = __popc(bal);
        __syncthreads();
        const int base = s_base;
        int wb = base;
        if (w > 0) wb += s_wcnt[0];
        if (w > 1) wb += s_wcnt[1];
        if (w > 2) wb += s_wcnt[2];
        if (pred) ent[wb + __popc(bal & ((1u << lane) - 1))] =
                      (unsigned)iv | dlb | ((unsigned)k << 27);
        if (tid == 0) hdr[k] = base;
        const int tot = s_wcnt[0] + s_wcnt[1] + s_wcnt[2] + s_wcnt[3];
        __syncthreads();
        if (tid == 0) s_base = base + tot;
    }
    __syncthreads();
    if (tid == 0) hdr[27] = s_base;
}

// ---------------- gather/zero over a round's contiguous entry range ----------
// A layout: 2 column-blocks of [128 rows x 64 bf16] (128B rows, sw128), block j
// at byte offset j*16384. K=128 per round.
template <int CIN, bool ZERO>
__device__ __forceinline__ void gpass(char* A, const unsigned* __restrict__ ent,
                                      int lo, int hi, int kr0, int tid,
                                      const uint4* __restrict__ in) {
    const uint4 z = make_uint4(0, 0, 0, 0);
    if (CIN == 8) {            // TPR=16, SUB=8: blk = tp>>3, tpl = tp&7 (16B each)
        for (int i = lo + tid; i < hi; i += 128) {
            unsigned e = ent[i];
            int tp = (int)(e >> 27) - kr0;
            int blk = tp >> 3, tpl = tp & 7;
            uint4 v = ZERO ? z : __ldg(in + (e & 0xFFFFFu));
            *(uint4*)(A + blk * 16384 + sw128(((e >> 20) & 127) * 128 + tpl * 16)) = v;
        }
    } else {                   // CIN=32: TPR=4, SUB=2: blk = tp>>1, tpl = tp&1 (64B each)
        for (int s = lo * 4 + tid; s < hi * 4; s += 128) {
            const int i = s >> 2, j = s & 3;
            unsigned e = ent[i];
            int tp = (int)(e >> 27) - kr0;
            int blk = tp >> 1, tpl = tp & 1;
            uint4 v = ZERO ? z : __ldg(in + (size_t)(e & 0xFFFFFu) * 4 + j);
            *(uint4*)(A + blk * 16384 + sw128(((e >> 20) & 127) * 128 + tpl * 64 + j * 16)) = v;
        }
    }
}

// ---------------- mma.sync sparse conv, K=128 rounds ----------------
// MODE 0: bf16 out = d ; MODE 1: bf16 out = x - d (NOUT=8) ; MODE 2: fp32 out = d + tile(x)
template <int CIN, int NOUT, int MODE>
__global__ __launch_bounds__(128) void conv_mma(const uint4* __restrict__ in,
        const uint4* __restrict__ wimg, const float* __restrict__ xres,
        void* __restrict__ outp) {
    constexpr int TPR = (CIN == 8) ? 16 : 4;
    constexpr int R = (KK + TPR - 1) / TPR;     // 2 or 7
    constexpr int NTL = NOUT / 8;
    __shared__ __align__(1024) __nv_bfloat16 sA[2 * MT * 64];    // 32KB
    __shared__ __align__(1024) __nv_bfloat16 sB[2 * NOUT * 64];  // 8KB / 2KB
    const int tile = blockIdx.x, tid = threadIdx.x, lane = tid & 31, wid = tid >> 5;
    const uint32_t abase = smem_u32(sA), bbase = smem_u32(sB);
    const int* __restrict__ hdr = g_hdr + tile * 28;
    const unsigned* __restrict__ ent = g_ent + (size_t)tile * ENTCAP;

    {   // zero A once; thereafter only active slots are nonzero
        uint4 zz = make_uint4(0, 0, 0, 0);
        uint4* a4 = (uint4*)sA;
#pragma unroll
        for (int i = 0; i < 16; i++) a4[tid + i * 128] = zz;
    }
    float acc[2][NTL][4];
#pragma unroll
    for (int mt = 0; mt < 2; mt++)
#pragma unroll
        for (int nt = 0; nt < NTL; nt++)
#pragma unroll
            for (int q = 0; q < 4; q++) acc[mt][nt][q] = 0.f;

    int plo = 0, phi = 0, pk0 = 0;
    for (int r = 0; r < R; r++) {
        const int kr0 = r * TPR;
        const int kend = (kr0 + TPR < KK) ? kr0 + TPR : KK;
        const int lo = hdr[kr0], hi = hdr[kend];
        if (r > 0) gpass<CIN, true>((char*)sA, ent, plo, phi, pk0, tid, in);
        __syncthreads();                       // zeros visible before new writes
        gpass<CIN, false>((char*)sA, ent, lo, hi, kr0, tid, in);
        for (int i = tid; i < 2 * NOUT * 8; i += 128)
            ((uint4*)sB)[i] = __ldg(wimg + 2 * r * NOUT * 8 + i);
        __syncthreads();                       // A/B ready
        const int m0 = wid * 32;
#pragma unroll
        for (int ks = 0; ks < 8; ks++) {
            const uint32_t ablk = abase + (ks >> 2) * 16384;
            const uint32_t bblk = bbase + (ks >> 2) * (NOUT * 128);
            const int ksl = ks & 3;
            uint32_t a[2][4];
#pragma unroll
            for (int mt = 0; mt < 2; mt++) {
                uint32_t addr = ablk + sw128((uint32_t)(m0 + mt * 16 + (lane & 15)) * 128
                                             + ksl * 32 + ((lane >> 4) * 16));
                ldsm4(a[mt], addr);
            }
#pragma unroll
            for (int nt = 0; nt < NTL; nt++) {
                uint32_t b[2];
                uint32_t baddr = bblk + sw128((uint32_t)(nt * 8 + (lane & 7)) * 128
                                              + ksl * 32 + (((lane >> 3) & 1) * 16));
                ldsm2(b, baddr);
                mma16816(acc[0][nt], a[0], b);
                mma16816(acc[1][nt], a[1], b);
            }
        }
        __syncthreads();                       // MMA reads done before next zeroing
        plo = lo; phi = hi; pk0 = kr0;
    }

    const int rbase = tile * 128 + wid * 32;
#pragma unroll
    for (int mt = 0; mt < 2; mt++) {
#pragma unroll
        for (int h = 0; h < 2; h++) {
            const int n = rbase + mt * 16 + (lane >> 2) + h * 8;
            if (n >= NV) continue;
            if (NOUT == 32) {
                if (MODE == 2) {
                    const float2 xr = *(const float2*)(xres + (size_t)n * 8 + (lane & 3) * 2);
                    float* o = (float*)outp + (size_t)n * 32 + (lane & 3) * 2;
#pragma unroll
                    for (int nt = 0; nt < NTL; nt++) {
                        float c0 = acc[mt][nt][h * 2], c1 = acc[mt][nt][h * 2 + 1];
                        *(float2*)(o + nt * 8) = make_float2(c0 + xr.x, c1 + xr.y);
                    }
                } else {
                    uint32_t* o = (uint32_t*)outp + (size_t)n * 16 + (lane & 3);
#pragma unroll
                    for (int nt = 0; nt < NTL; nt++)
                        o[nt * 4] = pkbf(acc[mt][nt][h * 2], acc[mt][nt][h * 2 + 1]);
                }
            } else {
                float c0 = acc[mt][0][h * 2], c1 = acc[mt][0][h * 2 + 1];
                if (MODE == 1) {
                    const float2 xr = *(const float2*)(xres + (size_t)n * 8 + (lane & 3) * 2);
                    c0 = xr.x - c0; c1 = xr.y - c1;
                }
                ((uint32_t*)outp)[(size_t)n * 4 + (lane & 3)] = pkbf(c0, c1);
            }
        }
    }
}

// ---------------- launcher ----------------
extern "C" void kernel_launch(void* const* d_in, const int* in_sizes, int n_in,
                              void* d_out, int out_size) {
    const float*         x    = (const float*)d_in[0];
    const int*           nidx = (const int*)d_in[1];
    const unsigned char* nmsk = (const unsigned char*)d_in[2];
    const float* Wd0 = (const float*)d_in[3];
    const float* Wd1 = (const float*)d_in[4];
    const float* Wd2 = (const float*)d_in[5];
    const float* Wu0 = (const float*)d_in[6];
    const float* Wu1 = (const float*)d_in[7];
    const float* Wu2 = (const float*)d_in[8];
    float* outp = (float*)d_out;

    void *p_xb, *p_t1, *p_t5, *p_sa, *p_sb, *p_w;
    cudaGetSymbolAddress(&p_xb, g_xb);
    cudaGetSymbolAddress(&p_t1, g_t1b);
    cudaGetSymbolAddress(&p_t5, g_t5b);
    cudaGetSymbolAddress(&p_sa, g_sab);
    cudaGetSymbolAddress(&p_sb, g_sbb);
    cudaGetSymbolAddress(&p_w,  g_wimg);
    const uint4* xb = (const uint4*)p_xb;
    uint4* t1b = (uint4*)p_t1;
    uint4* t5b = (uint4*)p_t5;
    uint4* sab = (uint4*)p_sa;
    uint4* sbb = (uint4*)p_sb;
    const uint4* wi = (const uint4*)p_w;   // bf16 offsets / 8

    // prep: 2 launches -> conv1 = #3, conv2 = #4 (ncu targets conv2 next)
    prep_wimg<<<56, 1024>>>(Wd0, Wd1, Wd2, Wu0, Wu1, Wu2, nmsk);
    prep_fill<<<NTILE, 128>>>(nmsk, nidx, x);

    // conv chain (wimg uint4 offsets: 0,1024,1920,2176,2432,3456)
    conv_mma<8, 32, 0><<<NTILE, 128>>>(xb, wi + 0, nullptr, t1b);                   // conv1
    conv_mma<32, 8, 0><<<NTILE, 128>>>((const uint4*)t1b, wi + 1024, nullptr, sab); // conv2
    conv_mma<8,  8, 1><<<NTILE, 128>>>((const uint4*)sab, wi + 1920, x, sbb);       // conv3
    conv_mma<8,  8, 0><<<NTILE, 128>>>((const uint4*)sbb, wi + 2176, nullptr, sab); // conv4
    conv_mma<8, 32, 0><<<NTILE, 128>>>((const uint4*)sab, wi + 2432, nullptr, t5b); // conv5
    conv_mma<32, 32, 2><<<NTILE, 128>>>((const uint4*)t5b, wi + 3456, x, outp);     // conv6
    (void)in_sizes; (void)n_in; (void)out_size;
}